// round 10
// baseline (speedup 1.0000x reference)
#include <cuda_runtime.h>
#include <cuda_bf16.h>

#define N_VOX 150000
#define C_IN  32
#define C_OUT 64
#define EPS   1e-5f

#define TILE_N    128
#define THREADS   256
#define NE        (26L * N_VOX)    // extras entries (all offsets except center)
#define SA_BLOCKS 592              // persistent tail grid (4 blocks/SM)
#define TOTAL4    (N_VOX * (C_OUT / 4))

// Cross-kernel scratch (no cudaMalloc allowed).
__device__ float g_sum[C_OUT];
__device__ float g_sq[C_OUT];
__device__ volatile unsigned g_flag;   // grid-barrier sense (monotonic)
__device__ unsigned g_cnt;             // grid-barrier arrival counter

// ---- packed f32x2 helpers -------------------------------------------------
__device__ __forceinline__ unsigned long long pack2(float x) {
    unsigned long long r;
    asm("mov.b64 %0, {%1, %1};" : "=l"(r) : "f"(x));
    return r;
}
__device__ __forceinline__ void unpack2(unsigned long long p, float& lo, float& hi) {
    asm("mov.b64 {%0, %1}, %2;" : "=f"(lo), "=f"(hi) : "l"(p));
}
__device__ __forceinline__ void fma2(unsigned long long& d,
                                     unsigned long long a, unsigned long long b) {
    asm("fma.rn.f32x2 %0, %1, %2, %0;" : "+l"(d) : "l"(a), "l"(b));
}

// ---------------------------------------------------------------------------
// K1: center offset (k=13; nbr[13][n]==n so gather is dense).
// FFMA2 microkernel, conflict-free:
//  - weights: scalar float4 LDS.128 from smem, duplicated to f32x2 in regs
//  - features: ulonglong2 LDS.128 (broadcast across half-warp)
// Thread (tc = t&15 cout quad, tr = t>>4) owns voxels 4tr+64j .. +3, j=0,1.
// ---------------------------------------------------------------------------
__global__ void __launch_bounds__(THREADS, 3)
center_kernel(const float* __restrict__ feat,
              const float* __restrict__ W,
              float* __restrict__ out)
{
    __shared__ __align__(16) float featS[C_IN][TILE_N + 4];  // 16896B, ci-major
    __shared__ __align__(16) float wS[C_IN][C_OUT];          // 8KB (W[13])

    const int t    = threadIdx.x;
    const int base = blockIdx.x * TILE_N;
    const int tc   = t & 15;   // cout quad: tc*4 .. tc*4+3
    const int tr   = t >> 4;   // 0..15

    // Stage weight slice W[13] (2048 floats = 512 float4)
    {
        const float4* Wk = reinterpret_cast<const float4*>(W + (size_t)13 * C_IN * C_OUT);
        float4* wS4 = reinterpret_cast<float4*>(&wS[0][0]);
        wS4[t]           = Wk[t];
        wS4[t + THREADS] = Wk[t + THREADS];
    }

    // Dense gather + transpose to ci-major
    const float4* f4 = reinterpret_cast<const float4*>(feat);
#pragma unroll
    for (int q = 0; q < 4; q++) {
        int lin  = t + THREADS * q;    // 0..1023
        int v    = lin >> 3;
        int part = lin & 7;
        float4 val = make_float4(0.f, 0.f, 0.f, 0.f);
        if (base + v < N_VOX)
            val = f4[(size_t)(base + v) * 8 + part];
        featS[part * 4 + 0][v] = val.x;
        featS[part * 4 + 1][v] = val.y;
        featS[part * 4 + 2][v] = val.z;
        featS[part * 4 + 3][v] = val.w;
    }
    __syncthreads();

    // acc2[j][p][c]: j = voxel group, p = pair within float4, c = cout
    unsigned long long acc2[2][2][4];
#pragma unroll
    for (int j = 0; j < 2; j++)
#pragma unroll
        for (int p = 0; p < 2; p++)
#pragma unroll
            for (int c = 0; c < 4; c++) acc2[j][p][c] = 0ull;

#pragma unroll
    for (int ci = 0; ci < C_IN; ci++) {
        float4 w = *reinterpret_cast<const float4*>(&wS[ci][tc * 4]);
        unsigned long long wp0 = pack2(w.x);
        unsigned long long wp1 = pack2(w.y);
        unsigned long long wp2 = pack2(w.z);
        unsigned long long wp3 = pack2(w.w);
#pragma unroll
        for (int j = 0; j < 2; j++) {
            ulonglong2 fp =
                *reinterpret_cast<const ulonglong2*>(&featS[ci][4 * tr + 64 * j]);
            fma2(acc2[j][0][0], fp.x, wp0);
            fma2(acc2[j][0][1], fp.x, wp1);
            fma2(acc2[j][0][2], fp.x, wp2);
            fma2(acc2[j][0][3], fp.x, wp3);
            fma2(acc2[j][1][0], fp.y, wp0);
            fma2(acc2[j][1][1], fp.y, wp1);
            fma2(acc2[j][1][2], fp.y, wp2);
            fma2(acc2[j][1][3], fp.y, wp3);
        }
    }

    // Write center-only result (extras phase accumulates on top later)
#pragma unroll
    for (int j = 0; j < 2; j++) {
#pragma unroll
        for (int p = 0; p < 2; p++) {
            float c0l, c0h, c1l, c1h, c2l, c2h, c3l, c3h;
            unpack2(acc2[j][p][0], c0l, c0h);
            unpack2(acc2[j][p][1], c1l, c1h);
            unpack2(acc2[j][p][2], c2l, c2h);
            unpack2(acc2[j][p][3], c3l, c3h);
            int v0 = base + 4 * tr + 64 * j + 2 * p;
            if (v0 < N_VOX)
                *reinterpret_cast<float4*>(out + (size_t)v0 * C_OUT + tc * 4) =
                    make_float4(c0l, c1l, c2l, c3l);
            if (v0 + 1 < N_VOX)
                *reinterpret_cast<float4*>(out + (size_t)(v0 + 1) * C_OUT + tc * 4) =
                    make_float4(c0h, c1h, c2h, c3h);
        }
    }
}

// ---------------------------------------------------------------------------
// K2: persistent tail: phase E (sparse extras) -> grid barrier ->
//     phase A (channel stats) -> grid barrier -> phase B (normalize+ReLU).
// ---------------------------------------------------------------------------
__device__ __forceinline__ void grid_barrier()
{
    __syncthreads();
    if (threadIdx.x == 0) {
        unsigned sense = g_flag;
        __threadfence();
        if (atomicAdd(&g_cnt, 1u) == SA_BLOCKS - 1) {
            g_cnt = 0;
            __threadfence();
            g_flag = sense + 1;     // release
        } else {
            while (g_flag == sense) { }
        }
    }
    __syncthreads();
}

__global__ void __launch_bounds__(THREADS, 4)
tail_kernel(const float* __restrict__ feat,
            const float* __restrict__ W,
            const int*   __restrict__ nbr,
            float* __restrict__ out,
            const float* __restrict__ gamma,
            const float* __restrict__ beta)
{
    __shared__ float sS[C_OUT];
    __shared__ float sQ[C_OUT];
    __shared__ float sSc[C_OUT];
    __shared__ float sB[C_OUT];

    const int t = threadIdx.x;
    if (blockIdx.x == 0 && t < C_OUT) { g_sum[t] = 0.f; g_sq[t] = 0.f; }
    if (t < C_OUT) { sS[t] = 0.f; sQ[t] = 0.f; }

    // ---- Phase E: sparse extras (grid-stride over 26 non-center rows) ----
    {
        const int lane = t & 31;
        const long gwarp  = (long)blockIdx.x * (THREADS / 32) + (t >> 5);
        const long wstride = (long)SA_BLOCKS * (THREADS / 32) * 32;
        const float2* W2 = reinterpret_cast<const float2*>(W);

        for (long eb = gwarp * 32; eb < NE; eb += wstride) {
            long e = eb + lane;
            int idx = -1, n = 0, k = 0;
            if (e < NE) {
                int kk = (int)(e / N_VOX);           // 0..25
                n  = (int)(e - (long)kk * N_VOX);
                k  = kk + (kk >= 13);                // skip center
                idx = nbr[(size_t)k * N_VOX + n];
            }
            unsigned bits = __ballot_sync(0xffffffffu, idx >= 0);
            while (bits) {
                int b = __ffs(bits) - 1;
                bits &= bits - 1;
                int ib = __shfl_sync(0xffffffffu, idx, b);
                int nb = __shfl_sync(0xffffffffu, n,   b);
                int kb = __shfl_sync(0xffffffffu, k,   b);

                float f = feat[(size_t)ib * C_IN + lane];   // lane = ci
                const float2* Wk = W2 + (size_t)kb * C_IN * (C_OUT / 2);
                float ax = 0.f, ay = 0.f;
#pragma unroll
                for (int ci = 0; ci < C_IN; ci++) {
                    float fv = __shfl_sync(0xffffffffu, f, ci);
                    float2 w = __ldg(&Wk[ci * (C_OUT / 2) + lane]);
                    ax = fmaf(fv, w.x, ax);
                    ay = fmaf(fv, w.y, ay);
                }
                float* o = out + (size_t)nb * C_OUT + 2 * lane;
                atomicAdd(o,     ax);
                atomicAdd(o + 1, ay);
            }
        }
    }

    grid_barrier();   // extras complete; g_sum/g_sq zeroing visible

    // ---- Phase A: per-channel sum/sumsq (out is L2-hot) ----
    const int gt     = blockIdx.x * THREADS + t;
    const int stride = SA_BLOCKS * THREADS;      // multiple of 16
    const int c4     = (gt & 15) * 4;
    const float4* o4c = reinterpret_cast<const float4*>(out);

    float4 s0 = make_float4(0.f, 0.f, 0.f, 0.f), q0 = s0;
    float4 s1 = s0, q1 = s0;
    for (int p = gt; p < TOTAL4; p += 2 * stride) {
        float4 x0 = o4c[p];
        s0.x += x0.x; s0.y += x0.y; s0.z += x0.z; s0.w += x0.w;
        q0.x += x0.x * x0.x; q0.y += x0.y * x0.y;
        q0.z += x0.z * x0.z; q0.w += x0.w * x0.w;
        int p1 = p + stride;
        if (p1 < TOTAL4) {
            float4 x1 = o4c[p1];
            s1.x += x1.x; s1.y += x1.y; s1.z += x1.z; s1.w += x1.w;
            q1.x += x1.x * x1.x; q1.y += x1.y * x1.y;
            q1.z += x1.z * x1.z; q1.w += x1.w * x1.w;
        }
    }
    s0.x += s1.x; s0.y += s1.y; s0.z += s1.z; s0.w += s1.w;
    q0.x += q1.x; q0.y += q1.y; q0.z += q1.z; q0.w += q1.w;

    atomicAdd(&sS[c4 + 0], s0.x); atomicAdd(&sS[c4 + 1], s0.y);
    atomicAdd(&sS[c4 + 2], s0.z); atomicAdd(&sS[c4 + 3], s0.w);
    atomicAdd(&sQ[c4 + 0], q0.x); atomicAdd(&sQ[c4 + 1], q0.y);
    atomicAdd(&sQ[c4 + 2], q0.z); atomicAdd(&sQ[c4 + 3], q0.w);
    __syncthreads();

    if (t < C_OUT) {
        atomicAdd(&g_sum[t], sS[t]);
        atomicAdd(&g_sq[t],  sQ[t]);
    }

    grid_barrier();

    if (t < C_OUT) {
        float sum, sq;
        asm("ld.global.cg.f32 %0, [%1];" : "=f"(sum) : "l"(&g_sum[t]));
        asm("ld.global.cg.f32 %0, [%1];" : "=f"(sq)  : "l"(&g_sq[t]));
        float mean = sum * (1.f / (float)N_VOX);
        float var  = sq * (1.f / (float)N_VOX) - mean * mean;
        var = fmaxf(var, 0.f);
        float sc = __ldg(&gamma[t]) * rsqrtf(var + EPS);
        sSc[t] = sc;
        sB[t]  = __ldg(&beta[t]) - mean * sc;
    }
    __syncthreads();

    // ---- Phase B: normalize + ReLU in place ----
    float4* o4 = reinterpret_cast<float4*>(out);
    for (int p = gt; p < TOTAL4; p += stride) {
        float4 x = o4[p];
        float4 sc = *reinterpret_cast<const float4*>(&sSc[c4]);
        float4 b  = *reinterpret_cast<const float4*>(&sB[c4]);
        x.x = fmaxf(fmaf(x.x, sc.x, b.x), 0.f);
        x.y = fmaxf(fmaf(x.y, sc.y, b.y), 0.f);
        x.z = fmaxf(fmaf(x.z, sc.z, b.z), 0.f);
        x.w = fmaxf(fmaf(x.w, sc.w, b.w), 0.f);
        o4[p] = x;
    }
}

extern "C" void kernel_launch(void* const* d_in, const int* in_sizes, int n_in,
                              void* d_out, int out_size)
{
    const float* features = (const float*)d_in[0];   // [150000, 32]
    const float* weight   = (const float*)d_in[1];   // [27, 32, 64]
    const float* gamma    = (const float*)d_in[2];   // [64]
    const float* beta     = (const float*)d_in[3];   // [64]
    const int*   nbr      = (const int*)d_in[4];     // [27, 150000]
    float* out = (float*)d_out;                      // [150000, 64]

    int gridC = (N_VOX + TILE_N - 1) / TILE_N;       // 1172
    center_kernel<<<gridC, THREADS>>>(features, weight, out);

    tail_kernel<<<SA_BLOCKS, THREADS>>>(features, weight, nbr, out, gamma, beta);
}

// round 11
// speedup vs baseline: 1.0105x; 1.0105x over previous
#include <cuda_runtime.h>
#include <cuda_bf16.h>

#define N_VOX 150000
#define C_IN  32
#define C_OUT 64
#define EPS   1e-5f

#define TILE_N    128
#define THREADS   256
#define NE        (26L * N_VOX)    // extras entries (all offsets except center)
#define SA_BLOCKS 592              // persistent tail grid (4 blocks/SM)
#define TOTAL4    (N_VOX * (C_OUT / 4))

// Cross-kernel scratch (no cudaMalloc allowed).
__device__ float g_sum[C_OUT];
__device__ float g_sq[C_OUT];
__device__ volatile unsigned g_flag;   // grid-barrier sense (monotonic)
__device__ unsigned g_cnt;             // grid-barrier arrival counter

// ---- packed f32x2 helpers -------------------------------------------------
__device__ __forceinline__ unsigned long long pack2(float x) {
    unsigned long long r;
    asm("mov.b64 %0, {%1, %1};" : "=l"(r) : "f"(x));
    return r;
}
__device__ __forceinline__ void unpack2(unsigned long long p, float& lo, float& hi) {
    asm("mov.b64 {%0, %1}, %2;" : "=f"(lo), "=f"(hi) : "l"(p));
}
__device__ __forceinline__ void fma2(unsigned long long& d,
                                     unsigned long long a, unsigned long long b) {
    asm("fma.rn.f32x2 %0, %1, %2, %0;" : "+l"(d) : "l"(a), "l"(b));
}

// ---------------------------------------------------------------------------
// K1: center offset (k=13; nbr[13][n]==n so gather is dense).
// FFMA2 microkernel, conflict-free:
//  - weights: scalar float4 LDS.128 from smem, duplicated to f32x2 in regs
//  - features: ulonglong2 LDS.128 (broadcast across half-warp)
// Thread (tc = t&15 cout quad, tr = t>>4) owns voxels 4tr+64j .. +3, j=0,1.
// ---------------------------------------------------------------------------
__global__ void __launch_bounds__(THREADS, 3)
center_kernel(const float* __restrict__ feat,
              const float* __restrict__ W,
              float* __restrict__ out)
{
    __shared__ __align__(16) float featS[C_IN][TILE_N + 4];  // 16896B, ci-major
    __shared__ __align__(16) float wS[C_IN][C_OUT];          // 8KB (W[13])

    const int t    = threadIdx.x;
    const int base = blockIdx.x * TILE_N;
    const int tc   = t & 15;   // cout quad: tc*4 .. tc*4+3
    const int tr   = t >> 4;   // 0..15

    // Stage weight slice W[13] (2048 floats = 512 float4)
    {
        const float4* Wk = reinterpret_cast<const float4*>(W + (size_t)13 * C_IN * C_OUT);
        float4* wS4 = reinterpret_cast<float4*>(&wS[0][0]);
        wS4[t]           = Wk[t];
        wS4[t + THREADS] = Wk[t + THREADS];
    }

    // Dense gather + transpose to ci-major
    const float4* f4 = reinterpret_cast<const float4*>(feat);
#pragma unroll
    for (int q = 0; q < 4; q++) {
        int lin  = t + THREADS * q;    // 0..1023
        int v    = lin >> 3;
        int part = lin & 7;
        float4 val = make_float4(0.f, 0.f, 0.f, 0.f);
        if (base + v < N_VOX)
            val = f4[(size_t)(base + v) * 8 + part];
        featS[part * 4 + 0][v] = val.x;
        featS[part * 4 + 1][v] = val.y;
        featS[part * 4 + 2][v] = val.z;
        featS[part * 4 + 3][v] = val.w;
    }
    __syncthreads();

    // acc2[j][p][c]: j = voxel group, p = pair within float4, c = cout
    unsigned long long acc2[2][2][4];
#pragma unroll
    for (int j = 0; j < 2; j++)
#pragma unroll
        for (int p = 0; p < 2; p++)
#pragma unroll
            for (int c = 0; c < 4; c++) acc2[j][p][c] = 0ull;

#pragma unroll
    for (int ci = 0; ci < C_IN; ci++) {
        float4 w = *reinterpret_cast<const float4*>(&wS[ci][tc * 4]);
        unsigned long long wp0 = pack2(w.x);
        unsigned long long wp1 = pack2(w.y);
        unsigned long long wp2 = pack2(w.z);
        unsigned long long wp3 = pack2(w.w);
#pragma unroll
        for (int j = 0; j < 2; j++) {
            ulonglong2 fp =
                *reinterpret_cast<const ulonglong2*>(&featS[ci][4 * tr + 64 * j]);
            fma2(acc2[j][0][0], fp.x, wp0);
            fma2(acc2[j][0][1], fp.x, wp1);
            fma2(acc2[j][0][2], fp.x, wp2);
            fma2(acc2[j][0][3], fp.x, wp3);
            fma2(acc2[j][1][0], fp.y, wp0);
            fma2(acc2[j][1][1], fp.y, wp1);
            fma2(acc2[j][1][2], fp.y, wp2);
            fma2(acc2[j][1][3], fp.y, wp3);
        }
    }

    // Write center-only result (extras phase accumulates on top later)
#pragma unroll
    for (int j = 0; j < 2; j++) {
#pragma unroll
        for (int p = 0; p < 2; p++) {
            float c0l, c0h, c1l, c1h, c2l, c2h, c3l, c3h;
            unpack2(acc2[j][p][0], c0l, c0h);
            unpack2(acc2[j][p][1], c1l, c1h);
            unpack2(acc2[j][p][2], c2l, c2h);
            unpack2(acc2[j][p][3], c3l, c3h);
            int v0 = base + 4 * tr + 64 * j + 2 * p;
            if (v0 < N_VOX)
                *reinterpret_cast<float4*>(out + (size_t)v0 * C_OUT + tc * 4) =
                    make_float4(c0l, c1l, c2l, c3l);
            if (v0 + 1 < N_VOX)
                *reinterpret_cast<float4*>(out + (size_t)(v0 + 1) * C_OUT + tc * 4) =
                    make_float4(c0h, c1h, c2h, c3h);
        }
    }
}

// ---------------------------------------------------------------------------
// K2: persistent tail: phase E (sparse extras) -> grid barrier ->
//     phase A (channel stats) -> grid barrier -> phase B (normalize+ReLU).
// ---------------------------------------------------------------------------
__device__ __forceinline__ void grid_barrier()
{
    __syncthreads();
    if (threadIdx.x == 0) {
        unsigned sense = g_flag;
        __threadfence();
        if (atomicAdd(&g_cnt, 1u) == SA_BLOCKS - 1) {
            g_cnt = 0;
            __threadfence();
            g_flag = sense + 1;     // release
        } else {
            while (g_flag == sense) { }
        }
    }
    __syncthreads();
}

__global__ void __launch_bounds__(THREADS, 4)
tail_kernel(const float* __restrict__ feat,
            const float* __restrict__ W,
            const int*   __restrict__ nbr,
            float* __restrict__ out,
            const float* __restrict__ gamma,
            const float* __restrict__ beta)
{
    __shared__ float sS[C_OUT];
    __shared__ float sQ[C_OUT];
    __shared__ float sSc[C_OUT];
    __shared__ float sB[C_OUT];

    const int t = threadIdx.x;
    if (blockIdx.x == 0 && t < C_OUT) { g_sum[t] = 0.f; g_sq[t] = 0.f; }
    if (t < C_OUT) { sS[t] = 0.f; sQ[t] = 0.f; }

    // ---- Phase E: sparse extras (grid-stride over 26 non-center rows) ----
    {
        const int lane = t & 31;
        const long gwarp  = (long)blockIdx.x * (THREADS / 32) + (t >> 5);
        const long wstride = (long)SA_BLOCKS * (THREADS / 32) * 32;
        const float2* W2 = reinterpret_cast<const float2*>(W);

        for (long eb = gwarp * 32; eb < NE; eb += wstride) {
            long e = eb + lane;
            int idx = -1, n = 0, k = 0;
            if (e < NE) {
                int kk = (int)(e / N_VOX);           // 0..25
                n  = (int)(e - (long)kk * N_VOX);
                k  = kk + (kk >= 13);                // skip center
                idx = nbr[(size_t)k * N_VOX + n];
            }
            unsigned bits = __ballot_sync(0xffffffffu, idx >= 0);
            while (bits) {
                int b = __ffs(bits) - 1;
                bits &= bits - 1;
                int ib = __shfl_sync(0xffffffffu, idx, b);
                int nb = __shfl_sync(0xffffffffu, n,   b);
                int kb = __shfl_sync(0xffffffffu, k,   b);

                float f = feat[(size_t)ib * C_IN + lane];   // lane = ci
                const float2* Wk = W2 + (size_t)kb * C_IN * (C_OUT / 2);
                float ax = 0.f, ay = 0.f;
#pragma unroll
                for (int ci = 0; ci < C_IN; ci++) {
                    float fv = __shfl_sync(0xffffffffu, f, ci);
                    float2 w = __ldg(&Wk[ci * (C_OUT / 2) + lane]);
                    ax = fmaf(fv, w.x, ax);
                    ay = fmaf(fv, w.y, ay);
                }
                float* o = out + (size_t)nb * C_OUT + 2 * lane;
                atomicAdd(o,     ax);
                atomicAdd(o + 1, ay);
            }
        }
    }

    grid_barrier();   // extras complete; g_sum/g_sq zeroing visible

    // ---- Phase A: per-channel sum/sumsq (out is L2-hot) ----
    const int gt     = blockIdx.x * THREADS + t;
    const int stride = SA_BLOCKS * THREADS;      // multiple of 16
    const int c4     = (gt & 15) * 4;
    const float4* o4c = reinterpret_cast<const float4*>(out);

    float4 s0 = make_float4(0.f, 0.f, 0.f, 0.f), q0 = s0;
    float4 s1 = s0, q1 = s0;
    for (int p = gt; p < TOTAL4; p += 2 * stride) {
        float4 x0 = o4c[p];
        s0.x += x0.x; s0.y += x0.y; s0.z += x0.z; s0.w += x0.w;
        q0.x += x0.x * x0.x; q0.y += x0.y * x0.y;
        q0.z += x0.z * x0.z; q0.w += x0.w * x0.w;
        int p1 = p + stride;
        if (p1 < TOTAL4) {
            float4 x1 = o4c[p1];
            s1.x += x1.x; s1.y += x1.y; s1.z += x1.z; s1.w += x1.w;
            q1.x += x1.x * x1.x; q1.y += x1.y * x1.y;
            q1.z += x1.z * x1.z; q1.w += x1.w * x1.w;
        }
    }
    s0.x += s1.x; s0.y += s1.y; s0.z += s1.z; s0.w += s1.w;
    q0.x += q1.x; q0.y += q1.y; q0.z += q1.z; q0.w += q1.w;

    atomicAdd(&sS[c4 + 0], s0.x); atomicAdd(&sS[c4 + 1], s0.y);
    atomicAdd(&sS[c4 + 2], s0.z); atomicAdd(&sS[c4 + 3], s0.w);
    atomicAdd(&sQ[c4 + 0], q0.x); atomicAdd(&sQ[c4 + 1], q0.y);
    atomicAdd(&sQ[c4 + 2], q0.z); atomicAdd(&sQ[c4 + 3], q0.w);
    __syncthreads();

    if (t < C_OUT) {
        atomicAdd(&g_sum[t], sS[t]);
        atomicAdd(&g_sq[t],  sQ[t]);
    }

    grid_barrier();

    if (t < C_OUT) {
        float sum, sq;
        asm("ld.global.cg.f32 %0, [%1];" : "=f"(sum) : "l"(&g_sum[t]));
        asm("ld.global.cg.f32 %0, [%1];" : "=f"(sq)  : "l"(&g_sq[t]));
        float mean = sum * (1.f / (float)N_VOX);
        float var  = sq * (1.f / (float)N_VOX) - mean * mean;
        var = fmaxf(var, 0.f);
        float sc = __ldg(&gamma[t]) * rsqrtf(var + EPS);
        sSc[t] = sc;
        sB[t]  = __ldg(&beta[t]) - mean * sc;
    }
    __syncthreads();

    // ---- Phase B: normalize + ReLU in place ----
    float4* o4 = reinterpret_cast<float4*>(out);
    for (int p = gt; p < TOTAL4; p += stride) {
        float4 x = o4[p];
        float4 sc = *reinterpret_cast<const float4*>(&sSc[c4]);
        float4 b  = *reinterpret_cast<const float4*>(&sB[c4]);
        x.x = fmaxf(fmaf(x.x, sc.x, b.x), 0.f);
        x.y = fmaxf(fmaf(x.y, sc.y, b.y), 0.f);
        x.z = fmaxf(fmaf(x.z, sc.z, b.z), 0.f);
        x.w = fmaxf(fmaf(x.w, sc.w, b.w), 0.f);
        o4[p] = x;
    }
}

extern "C" void kernel_launch(void* const* d_in, const int* in_sizes, int n_in,
                              void* d_out, int out_size)
{
    const float* features = (const float*)d_in[0];   // [150000, 32]
    const float* weight   = (const float*)d_in[1];   // [27, 32, 64]
    const float* gamma    = (const float*)d_in[2];   // [64]
    const float* beta     = (const float*)d_in[3];   // [64]
    const int*   nbr      = (const int*)d_in[4];     // [27, 150000]
    float* out = (float*)d_out;                      // [150000, 64]

    int gridC = (N_VOX + TILE_N - 1) / TILE_N;       // 1172
    center_kernel<<<gridC, THREADS>>>(features, weight, out);

    tail_kernel<<<SA_BLOCKS, THREADS>>>(features, weight, nbr, out, gamma, beta);
}